// round 10
// baseline (speedup 1.0000x reference)
#include <cuda_runtime.h>
#include <cuda_bf16.h>
#include <mma.h>
#include <cstdint>

using namespace nvcuda;

#define NN 100000
#define NE 1600000
#define DD 128
#define NG 64
#define NL 7
#define LEAKY 0.01f
#define BN_EPS 1e-5f

#define SCAN_BLK 256
#define SCAN_NB ((NN + SCAN_BLK - 1) / SCAN_BLK)   // 391
#define GATHER_BLOCKS 592                           // 4 per SM

// ---- wmma GEMM config ----
#define GT_GRID ((NN + 127) / 128)                  // 782
#define LDA 136                                      // bf16 leading dim (mult of 8, +skew)
#define LDB_F 136                                    // bias tile float ld
// byte offsets in dynamic smem
#define SM_AHI 0
#define SM_ALO 34816
#define SM_WHI 69632
#define SM_WLO 104448
#define SM_BIAS 139264
#define GT_SMEM_BYTES 147968

// ---------------- scratch (static device globals; no allocation) ----------------
__device__ __align__(16) float  g_T[(size_t)NN * DD];     // GEMM output (messages source)
__device__ __align__(16) float  g_AGG[(size_t)NN * DD];   // aggregated (pre-activation)
__device__ int    g_cnt[NN];
__device__ int    g_rowptr[NN + 1];
__device__ int    g_bsum[SCAN_NB];
__device__ int    g_boff[SCAN_NB];
__device__ int    g_col[NE];
__device__ float  g_w[NE];
__device__ float  g_dinv[NN];
__device__ double g_sum[DD], g_sq[DD];
__device__ __align__(16) __nv_bfloat16 g_Whi[DD * DD];    // W^T split-hi, row-major [n][k]
__device__ __align__(16) __nv_bfloat16 g_Wlo[DD * DD];    // W^T split-lo
__device__ float  g_bf[DD];
__device__ float  g_a[DD], g_c[DD];
__device__ float  g_pool[NG * DD];
__device__ float  g_pcnt[NG];
__device__ int    g_is64_ei, g_is64_batch;

__device__ __forceinline__ float leaky_f(float v) { return v > 0.f ? v : LEAKY * v; }

__device__ __forceinline__ int load_idx(const void* p, long long i, int is64) {
    return is64 ? (int)((const long long*)p)[i] : ((const int*)p)[i];
}

// split fp32 -> (hi, lo) bf16, two values packed into u32 pairs (elem0 in low bits)
__device__ __forceinline__ void split2(float v0, float v1, uint32_t& hi, uint32_t& lo) {
    __nv_bfloat16 h0 = __float2bfloat16(v0);
    __nv_bfloat16 h1 = __float2bfloat16(v1);
    __nv_bfloat16 l0 = __float2bfloat16(v0 - __bfloat162float(h0));
    __nv_bfloat16 l1 = __float2bfloat16(v1 - __bfloat162float(h1));
    hi = ((uint32_t)__bfloat16_as_ushort(h1) << 16) | __bfloat16_as_ushort(h0);
    lo = ((uint32_t)__bfloat16_as_ushort(l1) << 16) | __bfloat16_as_ushort(l0);
}

// W^T split store: [n=j][k] row-major
__device__ __forceinline__ void store_wsplit(int k, int j, float v) {
    __nv_bfloat16 hi = __float2bfloat16(v);
    __nv_bfloat16 lo = __float2bfloat16(v - __bfloat162float(hi));
    g_Whi[j * 128 + k] = hi;
    g_Wlo[j * 128 + k] = lo;
}

// ---------------- dtype probe (warp-parallel) ----------------
#define PROBE_WORDS 2048
#define PROBE_THRESH 900
__global__ void detect_kernel(const int* __restrict__ ei_w,
                              const int* __restrict__ batch_w) {
    int lane = threadIdx.x & 31;
    int z = 0;
    for (int i = 1 + 2 * lane; i < PROBE_WORDS; i += 64)
        if (ei_w[i] == 0) z++;
    #pragma unroll
    for (int o = 16; o > 0; o >>= 1) z += __shfl_xor_sync(0xFFFFFFFFu, z, o);
    if (lane == 0) g_is64_ei = (z > PROBE_THRESH / 2) ? 1 : 0;
    int z2 = 0;
    const int base = NN / 2;
    for (int i = 1 + 2 * lane; i < PROBE_WORDS; i += 64)
        if (batch_w[base + i] == 0) z2++;
    #pragma unroll
    for (int o = 16; o > 0; o >>= 1) z2 += __shfl_xor_sync(0xFFFFFFFFu, z2, o);
    if (lane == 0) g_is64_batch = (z2 > PROBE_THRESH / 2) ? 1 : 0;
}

// ---------------- pre-pass kernels ----------------
__global__ void zero_kernel() {
    int idx = blockIdx.x * blockDim.x + threadIdx.x;
    if (idx < NN) g_cnt[idx] = 0;
    if (idx < NG * DD) g_pool[idx] = 0.f;
    if (idx < NG) g_pcnt[idx] = 0.f;
}

__global__ void hist_kernel(const void* __restrict__ ei) {
    int e = blockIdx.x * blockDim.x + threadIdx.x;
    if (e >= NE) return;
    int d = load_idx(ei, (long long)NE + e, g_is64_ei);
    atomicAdd(&g_cnt[d], 1);
}

__global__ void scan1_kernel() {
    __shared__ int wsum[8];
    int idx = blockIdx.x * SCAN_BLK + threadIdx.x;
    int lane = threadIdx.x & 31, wid = threadIdx.x >> 5;
    int v = (idx < NN) ? g_cnt[idx] : 0;
    int x = v;
    #pragma unroll
    for (int o = 1; o < 32; o <<= 1) {
        int y = __shfl_up_sync(0xFFFFFFFFu, x, o);
        if (lane >= o) x += y;
    }
    if (lane == 31) wsum[wid] = x;
    __syncthreads();
    if (wid == 0 && lane < 8) {
        int s = wsum[lane];
        #pragma unroll
        for (int o = 1; o < 8; o <<= 1) {
            int y = __shfl_up_sync(0xFFu, s, o);
            if (lane >= o) s += y;
        }
        wsum[lane] = s;
    }
    __syncthreads();
    int excl = x - v + (wid > 0 ? wsum[wid - 1] : 0);
    if (idx < NN) {
        g_rowptr[idx] = excl;
        g_dinv[idx] = rsqrtf((float)(v + 1));
    }
    if (threadIdx.x == SCAN_BLK - 1) g_bsum[blockIdx.x] = excl + v;
}

__global__ void scan2_kernel() {
    __shared__ int sh[SCAN_NB];
    int tid = threadIdx.x;
    if (tid < SCAN_NB) sh[tid] = g_bsum[tid];
    __syncthreads();
    for (int o = 1; o < SCAN_NB; o <<= 1) {
        int val = 0;
        if (tid < SCAN_NB && tid >= o) val = sh[tid - o];
        __syncthreads();
        if (tid < SCAN_NB) sh[tid] += val;
        __syncthreads();
    }
    if (tid < SCAN_NB) g_boff[tid] = (tid > 0) ? sh[tid - 1] : 0;
    if (tid == 0) g_rowptr[NN] = sh[SCAN_NB - 1];
}

__global__ void scan3_kernel() {
    int idx = blockIdx.x * SCAN_BLK + threadIdx.x;
    if (idx >= NN) return;
    int r = g_rowptr[idx] + g_boff[blockIdx.x];
    g_rowptr[idx] = r;
    g_cnt[idx] = r;
}

__global__ void fill_kernel(const void* __restrict__ ei) {
    int e = blockIdx.x * blockDim.x + threadIdx.x;
    if (e >= NE) return;
    int is64 = g_is64_ei;
    int s = load_idx(ei, e, is64);
    int d = load_idx(ei, (long long)NE + e, is64);
    int pos = atomicAdd(&g_cnt[d], 1);
    g_col[pos] = s;
    g_w[pos] = g_dinv[s] * g_dinv[d];
}

// layer-0 weight split (+ zero stat accumulators before the first gather)
__global__ void w0prep_kernel(const float* __restrict__ W0) {
    int j = threadIdx.x;
    g_sum[j] = 0.0; g_sq[j] = 0.0;
    for (int k = 0; k < 128; k++) store_wsplit(k, j, W0[k * 128 + j]);
}

// ---------------- split-bf16 wmma GEMM: T = f(A) @ W + b ----------------
// Block: 256 thr (8 warps), 128x128 tile. Warp: 32 rows x 64 cols = 2x4 wmma tiles.
__global__ __launch_bounds__(256) void gemm_tc(const float* __restrict__ x0,
                                               const float* __restrict__ b0,
                                               int layer) {
    extern __shared__ char smem[];
    const float* __restrict__ A    = layer ? g_AGG : x0;
    const float* __restrict__ bias = layer ? g_bf  : b0;
    int tid = threadIdx.x;
    int row0 = blockIdx.x * 128;

    __nv_bfloat16* sAhi = (__nv_bfloat16*)(smem + SM_AHI);
    __nv_bfloat16* sAlo = (__nv_bfloat16*)(smem + SM_ALO);
    __nv_bfloat16* sWhi = (__nv_bfloat16*)(smem + SM_WHI);
    __nv_bfloat16* sWlo = (__nv_bfloat16*)(smem + SM_WLO);
    float*         sBias = (float*)(smem + SM_BIAS);

    // bias broadcast tile: 16 rows x 128 cols, ld LDB_F
    for (int i = tid; i < 2048; i += 256) {
        int r = i >> 7, c = i & 127;
        sBias[r * LDB_F + c] = bias[c];
    }

    // copy pre-split W^T [n][k] into SMEM rows (B col-major with ld=LDA)
    {
        const uint32_t* wh = (const uint32_t*)g_Whi;
        const uint32_t* wl = (const uint32_t*)g_Wlo;
        uint32_t* dh = (uint32_t*)sWhi;
        uint32_t* dl = (uint32_t*)sWlo;
        for (int i = tid; i < 8192; i += 256) {
            int n = i >> 6, kp = i & 63;
            dh[n * (LDA / 2) + kp] = wh[i];
            dl[n * (LDA / 2) + kp] = wl[i];
        }
    }

    // stage A tile: fp32 global (coalesced float4) -> leaky -> split bf16
    {
        const float4* A4 = (const float4*)A;
        uint32_t* ah = (uint32_t*)sAhi;
        uint32_t* al = (uint32_t*)sAlo;
        for (int i = tid; i < 4096; i += 256) {
            int r = i >> 5, q = i & 31;
            int row = row0 + r;
            float4 v = make_float4(0.f, 0.f, 0.f, 0.f);
            if (row < NN) v = A4[(size_t)row * 32 + q];
            if (layer) {
                v.x = leaky_f(v.x); v.y = leaky_f(v.y);
                v.z = leaky_f(v.z); v.w = leaky_f(v.w);
            }
            uint32_t h0, l0, h1, l1;
            split2(v.x, v.y, h0, l0);
            split2(v.z, v.w, h1, l1);
            int b = r * (LDA / 2) + q * 2;
            ah[b] = h0; ah[b + 1] = h1;
            al[b] = l0; al[b + 1] = l1;
        }
    }
    __syncthreads();

    int warp = tid >> 5;
    int rowbase = (warp >> 1) * 32;      // 0,32,64,96
    int colbase = (warp & 1) * 64;       // 0,64

    wmma::fragment<wmma::accumulator, 16, 16, 16, float> acc[2][4];
    #pragma unroll
    for (int r = 0; r < 2; r++)
        #pragma unroll
        for (int c = 0; c < 4; c++)
            wmma::load_matrix_sync(acc[r][c], sBias + colbase + c * 16, LDB_F,
                                   wmma::mem_row_major);

    #pragma unroll
    for (int k0 = 0; k0 < 8; k0++) {
        wmma::fragment<wmma::matrix_a, 16, 16, 16, __nv_bfloat16, wmma::row_major> aH[2], aL[2];
        wmma::fragment<wmma::matrix_b, 16, 16, 16, __nv_bfloat16, wmma::col_major> bH[4], bL[4];
        #pragma unroll
        for (int r = 0; r < 2; r++) {
            const __nv_bfloat16* pa = sAhi + (rowbase + r * 16) * LDA + k0 * 16;
            const __nv_bfloat16* pl = sAlo + (rowbase + r * 16) * LDA + k0 * 16;
            wmma::load_matrix_sync(aH[r], pa, LDA);
            wmma::load_matrix_sync(aL[r], pl, LDA);
        }
        #pragma unroll
        for (int c = 0; c < 4; c++) {
            const __nv_bfloat16* pb = sWhi + (colbase + c * 16) * LDA + k0 * 16;
            const __nv_bfloat16* pl = sWlo + (colbase + c * 16) * LDA + k0 * 16;
            wmma::load_matrix_sync(bH[c], pb, LDA);
            wmma::load_matrix_sync(bL[c], pl, LDA);
        }
        #pragma unroll
        for (int r = 0; r < 2; r++)
            #pragma unroll
            for (int c = 0; c < 4; c++) {
                wmma::mma_sync(acc[r][c], aH[r], bH[c], acc[r][c]);
                wmma::mma_sync(acc[r][c], aL[r], bH[c], acc[r][c]);
                wmma::mma_sync(acc[r][c], aH[r], bL[c], acc[r][c]);
            }
    }

    // store: NN % 16 == 0 so tile-granular guard is exact
    #pragma unroll
    for (int r = 0; r < 2; r++) {
        int rowt = row0 + rowbase + r * 16;
        if (rowt < NN) {
            #pragma unroll
            for (int c = 0; c < 4; c++)
                wmma::store_matrix_sync(g_T + (size_t)rowt * 128 + colbase + c * 16,
                                        acc[r][c], 128, wmma::mem_row_major);
        }
    }
}

// ---------------- persistent gather + fused channel stats ----------------
__global__ __launch_bounds__(256) void gather_kernel() {
    int lane = threadIdx.x & 31;
    int gwarp = blockIdx.x * 8 + (threadIdx.x >> 5);
    const int nwarps = GATHER_BLOCKS * 8;
    const float4* T4 = (const float4*)g_T;

    float4 ssum = make_float4(0.f, 0.f, 0.f, 0.f);
    float4 ssq  = make_float4(0.f, 0.f, 0.f, 0.f);

    for (int v = gwarp; v < NN; v += nwarps) {
        int beg = g_rowptr[v], end = g_rowptr[v + 1];
        float dv = g_dinv[v];
        float4 acc = T4[(size_t)v * 32 + lane];
        float s2 = dv * dv;
        acc.x *= s2; acc.y *= s2; acc.z *= s2; acc.w *= s2;
        int i = beg;
        for (; i + 4 <= end; i += 4) {
            int s0 = g_col[i], s1 = g_col[i + 1], s2i = g_col[i + 2], s3 = g_col[i + 3];
            float w0 = g_w[i], w1 = g_w[i + 1], w2 = g_w[i + 2], w3 = g_w[i + 3];
            float4 t0 = T4[(size_t)s0 * 32 + lane];
            float4 t1 = T4[(size_t)s1 * 32 + lane];
            float4 t2 = T4[(size_t)s2i * 32 + lane];
            float4 t3 = T4[(size_t)s3 * 32 + lane];
            acc.x += w0 * t0.x + w1 * t1.x + w2 * t2.x + w3 * t3.x;
            acc.y += w0 * t0.y + w1 * t1.y + w2 * t2.y + w3 * t3.y;
            acc.z += w0 * t0.z + w1 * t1.z + w2 * t2.z + w3 * t3.z;
            acc.w += w0 * t0.w + w1 * t1.w + w2 * t2.w + w3 * t3.w;
        }
        for (; i < end; i++) {
            int s = g_col[i]; float wt = g_w[i];
            float4 t = T4[(size_t)s * 32 + lane];
            acc.x += wt * t.x; acc.y += wt * t.y; acc.z += wt * t.z; acc.w += wt * t.w;
        }
        ((float4*)g_AGG)[(size_t)v * 32 + lane] = acc;
        float lx = leaky_f(acc.x), ly = leaky_f(acc.y);
        float lz = leaky_f(acc.z), lw = leaky_f(acc.w);
        ssum.x += lx; ssum.y += ly; ssum.z += lz; ssum.w += lw;
        ssq.x += lx * lx; ssq.y += ly * ly; ssq.z += lz * lz; ssq.w += lw * lw;
    }

    __shared__ float bsum[128], bsq[128];
    if (threadIdx.x < 128) { bsum[threadIdx.x] = 0.f; bsq[threadIdx.x] = 0.f; }
    __syncthreads();
    int c0 = lane * 4;
    atomicAdd(&bsum[c0 + 0], ssum.x); atomicAdd(&bsq[c0 + 0], ssq.x);
    atomicAdd(&bsum[c0 + 1], ssum.y); atomicAdd(&bsq[c0 + 1], ssq.y);
    atomicAdd(&bsum[c0 + 2], ssum.z); atomicAdd(&bsq[c0 + 2], ssq.z);
    atomicAdd(&bsum[c0 + 3], ssum.w); atomicAdd(&bsq[c0 + 3], ssq.w);
    __syncthreads();
    if (threadIdx.x < 128) {
        atomicAdd(&g_sum[threadIdx.x], (double)bsum[threadIdx.x]);
        atomicAdd(&g_sq[threadIdx.x], (double)bsq[threadIdx.x]);
    }
}

// fold BN affine of layer i into next layer's split weights (or keep a,c for last)
__global__ void fold_kernel(const float* __restrict__ Wnext,
                            const float* __restrict__ bnext,
                            const float* __restrict__ gamma,
                            const float* __restrict__ beta,
                            int isLast) {
    int j = threadIdx.x;
    float mu = (float)(g_sum[j] / (double)NN);
    float var = (float)(g_sq[j] / (double)NN - (double)mu * (double)mu);
    var = fmaxf(var, 0.f);
    float a = gamma[j] * rsqrtf(var + BN_EPS);
    float cc = beta[j] - mu * a;
    __shared__ float sa[128], sc[128];
    sa[j] = a; sc[j] = cc;
    __syncthreads();
    g_sum[j] = 0.0; g_sq[j] = 0.0;   // reset for next layer's gather
    if (isLast) { g_a[j] = a; g_c[j] = cc; return; }
    float bacc = bnext[j];
    for (int k = 0; k < 128; k++) {
        float wraw = Wnext[k * 128 + j];          // raw weight
        store_wsplit(k, j, sa[k] * wraw);         // scaled weight into W'
        bacc += sc[k] * wraw;                     // bias uses RAW weight (R8/R9 bug fixed)
    }
    g_bf[j] = bacc;
}

// run-length pooling over sorted batch ids
__global__ void pool_kernel(const void* __restrict__ batch) {
    int c = threadIdx.x;
    int r0 = blockIdx.x * 128;
    int rend = min(r0 + 128, NN);
    int is64 = g_is64_batch;
    float a = g_a[c], cc = g_c[c];
    int curg = load_idx(batch, r0, is64);
    float acc = 0.f; int run = 0;
    for (int r = r0; r < rend; r++) {
        int g = load_idx(batch, r, is64);
        if (g != curg) {
            atomicAdd(&g_pool[curg * 128 + c], acc);
            if (c == 0) atomicAdd(&g_pcnt[curg], (float)run);
            acc = 0.f; run = 0; curg = g;
        }
        float v = leaky_f(g_AGG[(size_t)r * 128 + c]);
        acc += v * a + cc;
        run++;
    }
    atomicAdd(&g_pool[curg * 128 + c], acc);
    if (c == 0) atomicAdd(&g_pcnt[curg], (float)run);
}

__global__ void final_kernel(float* __restrict__ out) {
    int idx = blockIdx.x * blockDim.x + threadIdx.x;
    if (idx < NG * DD) {
        int g = idx >> 7;
        out[idx] = g_pool[idx] / fmaxf(g_pcnt[g], 1.f);
    }
}

// ---------------- launch ----------------
extern "C" void kernel_launch(void* const* d_in, const int* in_sizes, int n_in,
                              void* d_out, int out_size) {
    const float* x = (const float*)d_in[0];
    const void* ei = d_in[1];
    const void* batch = d_in[2];
    const float* Ws = (const float*)d_in[3];
    const float* bs = (const float*)d_in[4];
    const float* gm = (const float*)d_in[5];
    const float* bt = (const float*)d_in[6];
    float* out = (float*)d_out;

    cudaFuncSetAttribute(gemm_tc, cudaFuncAttributeMaxDynamicSharedMemorySize,
                         GT_SMEM_BYTES);

    detect_kernel<<<1, 32>>>((const int*)ei, (const int*)batch);
    zero_kernel<<<(NN + 255) / 256, 256>>>();
    hist_kernel<<<(NE + 255) / 256, 256>>>(ei);
    scan1_kernel<<<SCAN_NB, SCAN_BLK>>>();
    scan2_kernel<<<1, 512>>>();
    scan3_kernel<<<SCAN_NB, SCAN_BLK>>>();
    fill_kernel<<<(NE + 255) / 256, 256>>>(ei);
    w0prep_kernel<<<1, 128>>>(Ws);

    for (int i = 0; i < NL; i++) {
        gemm_tc<<<GT_GRID, 256, GT_SMEM_BYTES>>>(x, bs, i);
        gather_kernel<<<GATHER_BLOCKS, 256>>>();
        int nxt = (i + 1 < NL) ? (i + 1) : 0;
        fold_kernel<<<1, 128>>>(Ws + (size_t)nxt * DD * DD, bs + (size_t)nxt * DD,
                                gm + (size_t)i * DD, bt + (size_t)i * DD,
                                (i == NL - 1) ? 1 : 0);
    }
    pool_kernel<<<(NN + 127) / 128, 128>>>(batch);
    final_kernel<<<(NG * DD + 255) / 256, 256>>>(out);
}